// round 14
// baseline (speedup 1.0000x reference)
#include <cuda_runtime.h>
#include <cuda_bf16.h>
#include <cstddef>
#include <cstdint>

#define TT   1024
#define BB   64
#define FF   512          // feature dim (== 2H, both layers share K=512)
#define HH   256
#define GXN  1280         // 5*H
#define RNB  32           // recurrence blocks: 2 dirs * 16 slices

// ---------------- scratch (device globals; no runtime allocation) ------------
__device__ float g_y  [(size_t)TT*BB*FF];        // layer-0 output / layer-1 input (fp32)
__device__ float g_fin[(size_t)TT*BB*FF];        // layer-1 output
__device__ float g_gx [2][(size_t)TT*BB*GXN];    // per-dir input-gate projections
__device__ float g_px [2][(size_t)TT*BB*HH];     // per-dir highway projections
// h exchange, pre-split bf16: [parity][dir][b][k]
__device__ __nv_bfloat16 g_hh[2][2][BB*HH];
__device__ __nv_bfloat16 g_hl[2][2][BB*HH];
__device__ unsigned g_bar;

// bf16 split operands for projections
__device__ __nv_bfloat16 g_xh[(size_t)TT*BB*FF], g_xl[(size_t)TT*BB*FF];
__device__ __nv_bfloat16 g_yh[(size_t)TT*BB*FF], g_yl[(size_t)TT*BB*FF];
__device__ __nv_bfloat16 g_wxh[2*2*FF*GXN], g_wxl[2*2*FF*GXN];
__device__ __nv_bfloat16 g_wph[2*2*FF*HH],  g_wpl[2*2*FF*HH];

// ---------------- helpers ----------------------------------------------------
__device__ __forceinline__ void split1(float x, __nv_bfloat16& h, __nv_bfloat16& l) {
    h = __float2bfloat16(x);
    l = __float2bfloat16(x - __bfloat162float(h));
}

// transpose+split: features [b][t][512] fp32 -> xh/xl [t][b][512] bf16
__global__ void k_tin(const float* __restrict__ feat,
                      __nv_bfloat16* __restrict__ xh, __nv_bfloat16* __restrict__ xl) {
    int row = blockIdx.x;               // b*T + t
    int b = row >> 10, t = row & 1023;
    float4 v = ((const float4*)(feat + (size_t)row * FF))[threadIdx.x];
    size_t drow = ((size_t)t * BB + b) * FF + threadIdx.x * 4;
    __nv_bfloat16 h4[4], l4[4];
    split1(v.x, h4[0], l4[0]); split1(v.y, h4[1], l4[1]);
    split1(v.z, h4[2], l4[2]); split1(v.w, h4[3], l4[3]);
    *(uint2*)(xh + drow) = *(uint2*)h4;
    *(uint2*)(xl + drow) = *(uint2*)l4;
}

// generic fp32 -> bf16 hi/lo split (n4 = element count / 4)
__global__ void k_split(const float* __restrict__ in,
                        __nv_bfloat16* __restrict__ hi, __nv_bfloat16* __restrict__ lo, int n4) {
    int i = blockIdx.x * blockDim.x + threadIdx.x;
    if (i >= n4) return;
    float4 v = ((const float4*)in)[i];
    __nv_bfloat16 h4[4], l4[4];
    split1(v.x, h4[0], l4[0]); split1(v.y, h4[1], l4[1]);
    split1(v.z, h4[2], l4[2]); split1(v.w, h4[3], l4[3]);
    *(uint2*)(hi + (size_t)i * 4) = *(uint2*)h4;
    *(uint2*)(lo + (size_t)i * 4) = *(uint2*)l4;
}

// transpose: fin [t][b][512] -> out [b][t][512]
__global__ void k_tout(const float* __restrict__ fin, float* __restrict__ out) {
    int row = blockIdx.x;               // t*B + b
    int t = row >> 6, b = row & 63;
    const float4* s = (const float4*)(fin + (size_t)row * FF);
    float4* d = (float4*)(out + (((size_t)b << 10) + t) * FF);
    for (int i = threadIdx.x; i < FF / 4; i += blockDim.x) d[i] = s[i];
}

// ---------------- PTX wrappers -----------------------------------------------
__device__ __forceinline__ void ldsm_x4(uint32_t* r, uint32_t a) {
    asm volatile("ldmatrix.sync.aligned.m8n8.x4.shared.b16 {%0,%1,%2,%3}, [%4];"
        : "=r"(r[0]), "=r"(r[1]), "=r"(r[2]), "=r"(r[3]) : "r"(a));
}
__device__ __forceinline__ void ldsm_x4_t(uint32_t* r, uint32_t a) {
    asm volatile("ldmatrix.sync.aligned.m8n8.x4.trans.shared.b16 {%0,%1,%2,%3}, [%4];"
        : "=r"(r[0]), "=r"(r[1]), "=r"(r[2]), "=r"(r[3]) : "r"(a));
}
__device__ __forceinline__ void mma_bf16(float* c, const uint32_t* a, const uint32_t* b) {
    asm volatile("mma.sync.aligned.m16n8k16.row.col.f32.bf16.bf16.f32 "
        "{%0,%1,%2,%3},{%4,%5,%6,%7},{%8,%9},{%0,%1,%2,%3};"
        : "+f"(c[0]), "+f"(c[1]), "+f"(c[2]), "+f"(c[3])
        : "r"(a[0]), "r"(a[1]), "r"(a[2]), "r"(a[3]), "r"(b[0]), "r"(b[1]));
}
__device__ __forceinline__ void cp16(uint32_t s, const void* g) {
    asm volatile("cp.async.cg.shared.global [%0], [%1], 16;" :: "r"(s), "l"(g));
}
#define CP_COMMIT asm volatile("cp.async.commit_group;")
#define CP_WAIT1  asm volatile("cp.async.wait_group 1;")
#define CP_WAIT0  asm volatile("cp.async.wait_group 0;")

// ---------------- tensor-core split-bf16 GEMM (unchanged, proven) -------------
#define STG_A 10240               // 128 rows * 80B pitch
#define STG_B 8192                // 32 rows * 256B, XOR-swizzled
#define STG_SZ (2*STG_A + 2*STG_B)
#define SMEM_MMA (2*STG_SZ)       // double-buffered: 73728 B

__global__ __launch_bounds__(256)
void k_mma(const __nv_bfloat16* __restrict__ Ah, const __nv_bfloat16* __restrict__ Al,
           const __nv_bfloat16* __restrict__ Bh, const __nv_bfloat16* __restrict__ Bl,
           const float* __restrict__ bias, float* __restrict__ C, int N, int K) {
    extern __shared__ char smem[];
    uint32_t su = (uint32_t)__cvta_generic_to_shared(smem);
    int tid = threadIdx.x, lane = tid & 31, wid = tid >> 5;
    int mw = wid & 3, nw = wid >> 2;          // 4x2 warp grid
    int m0 = blockIdx.y * 128, n0 = blockIdx.x * 128;

    float acc[2][8][4];
#pragma unroll
    for (int mi = 0; mi < 2; mi++)
#pragma unroll
        for (int j = 0; j < 8; j++)
#pragma unroll
            for (int q = 0; q < 4; q++) acc[mi][j][q] = 0.f;

    auto load_stage = [&](int st, int k0) {
        uint32_t sa = su + st * STG_SZ;
#pragma unroll
        for (int hl = 0; hl < 2; hl++) {
            const __nv_bfloat16* Ap = hl ? Al : Ah;
            uint32_t sb = sa + hl * STG_A;
#pragma unroll
            for (int rep = 0; rep < 2; rep++) {
                int idx = tid + rep * 256;          // 0..511
                int r = idx >> 2, c = idx & 3;
                cp16(sb + r * 80 + c * 16, Ap + (size_t)(m0 + r) * K + k0 + c * 8);
            }
        }
#pragma unroll
        for (int hl = 0; hl < 2; hl++) {
            const __nv_bfloat16* Bp = hl ? Bl : Bh;
            uint32_t sb = sa + 2 * STG_A + hl * STG_B;
#pragma unroll
            for (int rep = 0; rep < 2; rep++) {
                int idx = tid + rep * 256;
                int k = idx >> 4, c = idx & 15;
                cp16(sb + k * 256 + ((c ^ (k & 7)) * 16),
                     Bp + (size_t)(k0 + k) * N + n0 + c * 8);
            }
        }
    };

    int NIT = K >> 5;                             // 16 for K=512
    load_stage(0, 0);
    CP_COMMIT;

    for (int it = 0; it < NIT; it++) {
        if (it + 1 < NIT) { load_stage((it + 1) & 1, (it + 1) * 32); CP_COMMIT; CP_WAIT1; }
        else              { CP_WAIT0; }
        __syncthreads();

        uint32_t sa = su + (it & 1) * STG_SZ;
#pragma unroll
        for (int kk = 0; kk < 2; kk++) {
            uint32_t ah[2][4], al[2][4];
            int arow_c = kk * 2 + (lane >> 4);
            int arow_r = (lane & 15);
#pragma unroll
            for (int mi = 0; mi < 2; mi++) {
                uint32_t ad = sa + (mw * 32 + mi * 16 + arow_r) * 80 + arow_c * 16;
                ldsm_x4(ah[mi], ad);
                ldsm_x4(al[mi], ad + STG_A);
            }
#pragma unroll
            for (int jp = 0; jp < 4; jp++) {
                int krow = kk * 16 + (lane & 15);
                int cch  = nw * 8 + jp * 2 + (lane >> 4);
                uint32_t bd = sa + 2 * STG_A + krow * 256 + ((cch ^ (krow & 7)) * 16);
                uint32_t bh[4], bl[4];
                ldsm_x4_t(bh, bd);
                ldsm_x4_t(bl, bd + STG_B);
#pragma unroll
                for (int jj = 0; jj < 2; jj++) {
#pragma unroll
                    for (int mi = 0; mi < 2; mi++) {
                        float* a4 = acc[mi][jp * 2 + jj];
                        mma_bf16(a4, ah[mi], &bh[jj * 2]);  // Ahi @ Bhi
                        mma_bf16(a4, ah[mi], &bl[jj * 2]);  // Ahi @ Blo
                        mma_bf16(a4, al[mi], &bh[jj * 2]);  // Alo @ Bhi
                    }
                }
            }
        }
        __syncthreads();
    }

#pragma unroll
    for (int mi = 0; mi < 2; mi++) {
#pragma unroll
        for (int j = 0; j < 8; j++) {
            int row = m0 + mw * 32 + mi * 16 + (lane >> 2);
            int col = n0 + nw * 64 + j * 8 + (lane & 3) * 2;
            float b0 = bias[col], b1 = bias[col + 1];
            float2 v0 = {acc[mi][j][0] + b0, acc[mi][j][1] + b1};
            float2 v1 = {acc[mi][j][2] + b0, acc[mi][j][3] + b1};
            *(float2*)(C + (size_t)row * N + col)       = v0;
            *(float2*)(C + (size_t)(row + 8) * N + col) = v1;
        }
    }
}

// ---------------- reset barrier + h buffers (before each recurrence) ---------
__global__ void k_reset() {
    int i = blockIdx.x * blockDim.x + threadIdx.x;
    if (i == 0) g_bar = 0u;
    if (i < 2 * 2 * BB * HH / 2) {        // 32768 u32 words per array
        ((uint32_t*)g_hh)[i] = 0u;
        ((uint32_t*)g_hl)[i] = 0u;
    }
}

// ---------------- persistent tensor-core bidirectional highway-LSTM scan -----
// grid = 32 blocks: blockIdx.x = d + 2*j  (d: direction, j: 16-col slice 0..15)
// block = 256 threads = 8 warps: warp = (m-tile mt = wid&3) x (k-half k2 = wid>>2)
// Per step:
//   1. stage pre-split h hi/lo (bf16, [b][k]) from L2 into smem (pitch 528)
//   2. mma m16n8k16 x 3 streams: z[64 b][80 n] = h @ Whslice  (n = gate*16+cc)
//   3. k-half partials combined via smem z (pitch 88 fp32, conflict-free);
//      gate threads (cc=tid&15, b0=tid>>4) handle 4 batches each, write
//      split h back to L2 + fp32 out
//   4. grid barrier (32 arrivals only)
// smem layout (bytes):
//   w_hi [256 k][176]  @ 0        (45056)   n-padded to 88, zeros beyond n=79
//   w_lo [256 k][176]  @ 45056    (45056)
//   h_hi [64 b][528]   @ 90112    (33792)
//   h_lo [64 b][528]   @ 123904   (33792)
//   z    [2 kh][64][88]@ 157696   (45056)
#define R_WHI 0
#define R_WLO 45056
#define R_HHI 90112
#define R_HLO 123904
#define R_Z   157696
#define REC_SMEM (R_Z + 2*64*88*4)   // 202752

__device__ __forceinline__ float sigf(float x) { return 1.f / (1.f + expf(-x)); }

__global__ __launch_bounds__(256, 1)
void k_rec(const float* __restrict__ Wh_l,   // [2][256][1280] (this layer)
           const float* __restrict__ bh_l,   // [2][1280]
           const float* __restrict__ gx0, const float* __restrict__ gx1,
           const float* __restrict__ px0, const float* __restrict__ px1,
           float* __restrict__ outbuf) {     // [t][b][512] (fwd|bwd concat)
    extern __shared__ char smc[];
    uint32_t su = (uint32_t)__cvta_generic_to_shared(smc);
    float* zbuf = (float*)(smc + R_Z);        // [2][64][88]

    int tid = threadIdx.x, lane = tid & 31, wid = tid >> 5;
    int d  = blockIdx.x & 1;
    int j  = blockIdx.x >> 1;                 // 0..15
    int mt = wid & 3, k2 = wid >> 2;          // warp roles
    int cc = tid & 15, b0 = tid >> 4;         // gate-thread: col cc, batches b0+16e
    int col = j * 16 + cc;

    const float* Wh_d = Wh_l + (size_t)d * HH * GXN;
    const float* gx = d ? gx1 : gx0;
    const float* px = d ? px1 : px0;

    // fill Wh slice, split hi/lo: rows k (pitch 176B), cols n=gate*16+cc (80, pad->88 zeros)
    for (int idx = tid; idx < 256 * 88; idx += 256) {
        int k = idx / 88, n = idx % 88;
        float v = 0.f;
        if (n < 80) v = Wh_d[(size_t)k * GXN + (n >> 4) * HH + j * 16 + (n & 15)];
        unsigned vb = __float_as_uint(v);
        unsigned short hib = (unsigned short)(vb >> 16);            // trunc split
        float lof = v - __uint_as_float(vb & 0xFFFF0000u);
        unsigned short lob;
        asm("cvt.rn.bf16.f32 %0, %1;" : "=h"(lob) : "f"(lof));
        ((unsigned short*)(smc + R_WHI + k * 176))[n] = hib;
        ((unsigned short*)(smc + R_WLO + k * 176))[n] = lob;
    }
    float bh5[5];
#pragma unroll
    for (int g = 0; g < 5; g++) bh5[g] = bh_l[(size_t)d * GXN + g * HH + col];

    float cs[4] = {0.f, 0.f, 0.f, 0.f};       // cell states (batches b0+16e)
    __syncthreads();

    for (int s = 0; s < TT; s++) {
        int t = d ? (TT - 1 - s) : s;
        size_t tb = (size_t)t * BB;

        // prefetch gate inputs for this thread's 4 elements (resolve during mma)
        float gxa[4][5], pxa[4];
#pragma unroll
        for (int e = 0; e < 4; e++) {
            int b = b0 + e * 16;
            size_t r0 = (tb + b) * GXN;
#pragma unroll
            for (int g = 0; g < 5; g++) gxa[e][g] = __ldg(gx + r0 + g * HH + col);
            pxa[e] = __ldg(px + (tb + b) * HH + col);
        }

        // stage h hi/lo from L2: thread (r=tid>>2, q=tid&3) copies 128B of each
        // stream; chunk rotation keeps the 528-pitch STS conflict-free.
        {
            int r = tid >> 2, q = tid & 3;
            const uint4* shi = (const uint4*)&g_hh[s & 1][d][0] + r * 32 + q * 8;
            const uint4* slo = (const uint4*)&g_hl[s & 1][d][0] + r * 32 + q * 8;
            char* dhi = smc + R_HHI + r * 528 + q * 128;
            char* dlo = smc + R_HLO + r * 528 + q * 128;
#pragma unroll
            for (int i = 0; i < 8; i++) {
                int i2 = (i + q * 2) & 7;
                *(uint4*)(dhi + i2 * 16) = __ldcg(shi + i2);
                *(uint4*)(dlo + i2 * 16) = __ldcg(slo + i2);
            }
        }
        __syncthreads();

        // mma: z[mt*16..+15 b][80 n] over k-half k2 (k = k2*128 .. +127)
        float acc[10][4];
#pragma unroll
        for (int nt = 0; nt < 10; nt++)
#pragma unroll
            for (int q = 0; q < 4; q++) acc[nt][q] = 0.f;

#pragma unroll
        for (int ks8 = 0; ks8 < 8; ks8++) {
            int ks = k2 * 8 + ks8;                // 16-k step index
            uint32_t ah[4], al[4];
            uint32_t aad = su + R_HHI + (mt * 16 + (lane & 15)) * 528
                         + ks * 32 + (lane >> 4) * 16;
            ldsm_x4(ah, aad);
            ldsm_x4(al, aad + (R_HLO - R_HHI));
            uint32_t brow = su + (ks * 16 + (lane & 15)) * 176 + (lane >> 4) * 16;
#pragma unroll
            for (int p = 0; p < 5; p++) {
                uint32_t bh[4], bl[4];
                ldsm_x4_t(bh, brow + R_WHI + p * 32);
                ldsm_x4_t(bl, brow + R_WLO + p * 32);
                mma_bf16(acc[p*2],   ah, &bh[0]); mma_bf16(acc[p*2],   ah, &bl[0]); mma_bf16(acc[p*2],   al, &bh[0]);
                mma_bf16(acc[p*2+1], ah, &bh[2]); mma_bf16(acc[p*2+1], ah, &bl[2]); mma_bf16(acc[p*2+1], al, &bh[2]);
            }
        }

        // store fragments to z[k2][batch][n]  (pitch 88 -> conflict-free phases)
        {
            float* zp = zbuf + k2 * (64 * 88);
            int row0 = mt * 16 + (lane >> 2);
            int col0 = (lane & 3) * 2;
#pragma unroll
            for (int nt = 0; nt < 10; nt++) {
                *(float2*)&zp[row0 * 88 + nt * 8 + col0]       = make_float2(acc[nt][0], acc[nt][1]);
                *(float2*)&zp[(row0 + 8) * 88 + nt * 8 + col0] = make_float2(acc[nt][2], acc[nt][3]);
            }
        }
        __syncthreads();

        // gates for 4 elements (col, b0+16e): z split order = i, o, f, u, r
#pragma unroll
        for (int e = 0; e < 4; e++) {
            int b = b0 + e * 16;
            float z5[5];
#pragma unroll
            for (int g = 0; g < 5; g++) {
                int n = g * 16 + cc;
                z5[g] = zbuf[b * 88 + n] + zbuf[64 * 88 + b * 88 + n];
            }
            float zi = z5[0] + gxa[e][0] + bh5[0];
            float zo = z5[1] + gxa[e][1] + bh5[1];
            float zf = z5[2] + gxa[e][2] + bh5[2];
            float zu = z5[3] + gxa[e][3] + bh5[3];
            float zr = z5[4] + gxa[e][4] + bh5[4];
            cs[e] = sigf(zi) * tanhf(zu) + sigf(zf) * cs[e];
            float hhv = sigf(zo) * tanhf(cs[e]);
            float rg  = sigf(zr);
            float hf  = rg * hhv + (1.f - rg) * pxa[e];

            // split hf -> bf16 hi (trunc) + lo (rn of residual), write via L2
            unsigned fb = __float_as_uint(hf);
            unsigned short hib = (unsigned short)(fb >> 16);
            float lof = hf - __uint_as_float(fb & 0xFFFF0000u);
            unsigned short lob;
            asm("cvt.rn.bf16.f32 %0, %1;" : "=h"(lob) : "f"(lof));
            __nv_bfloat16* dh = &g_hh[(s + 1) & 1][d][b * HH + col];
            __nv_bfloat16* dl = &g_hl[(s + 1) & 1][d][b * HH + col];
            asm volatile("st.global.cg.u16 [%0], %1;" :: "l"(dh), "h"(hib) : "memory");
            asm volatile("st.global.cg.u16 [%0], %1;" :: "l"(dl), "h"(lob) : "memory");
            outbuf[(tb + b) * FF + d * HH + col] = hf;
        }

        // grid barrier: make h stores visible, arrive, spin (only 32 arrivals)
        __threadfence();
        __syncthreads();
        if (tid == 0) {
            atomicAdd(&g_bar, 1u);
            unsigned target = (unsigned)(s + 1) * RNB;
            volatile unsigned* vb = &g_bar;
            while (*vb < target) __nanosleep(32);
        }
        __syncthreads();
    }
}

// ---------------------------- host driver ------------------------------------
extern "C" void kernel_launch(void* const* d_in, const int* in_sizes, int n_in,
                              void* d_out, int out_size) {
    (void)in_sizes; (void)n_in; (void)out_size;
    const float* feat = (const float*)d_in[0];
    const float* Wx   = (const float*)d_in[1];  // [2][2][512][1280]
    const float* bx   = (const float*)d_in[2];  // [2][2][1280]
    const float* Wh   = (const float*)d_in[3];  // [2][2][256][1280]
    const float* bh   = (const float*)d_in[4];  // [2][2][1280]
    const float* Wp   = (const float*)d_in[5];  // [2][2][512][256]
    const float* bp   = (const float*)d_in[6];  // [2][2][256]
    float* out = (float*)d_out;

    float *p_y, *p_f, *p_gx, *p_px;
    __nv_bfloat16 *p_xh, *p_xl, *p_yh, *p_yl, *p_wxh, *p_wxl, *p_wph, *p_wpl;
    cudaGetSymbolAddress((void**)&p_y,   g_y);
    cudaGetSymbolAddress((void**)&p_f,   g_fin);
    cudaGetSymbolAddress((void**)&p_gx,  g_gx);
    cudaGetSymbolAddress((void**)&p_px,  g_px);
    cudaGetSymbolAddress((void**)&p_xh,  g_xh);
    cudaGetSymbolAddress((void**)&p_xl,  g_xl);
    cudaGetSymbolAddress((void**)&p_yh,  g_yh);
    cudaGetSymbolAddress((void**)&p_yl,  g_yl);
    cudaGetSymbolAddress((void**)&p_wxh, g_wxh);
    cudaGetSymbolAddress((void**)&p_wxl, g_wxl);
    cudaGetSymbolAddress((void**)&p_wph, g_wph);
    cudaGetSymbolAddress((void**)&p_wpl, g_wpl);

    cudaFuncSetAttribute(k_rec, cudaFuncAttributeMaxDynamicSharedMemorySize, REC_SMEM);
    cudaFuncSetAttribute(k_mma, cudaFuncAttributeMaxDynamicSharedMemorySize, SMEM_MMA);

    const size_t GXSZ = (size_t)TT * BB * GXN;
    const size_t PXSZ = (size_t)TT * BB * HH;

    k_tin<<<TT * BB, 128>>>(feat, p_xh, p_xl);
    k_split<<<(2 * 2 * FF * GXN / 4 + 255) / 256, 256>>>(Wx, p_wxh, p_wxl, 2 * 2 * FF * GXN / 4);
    k_split<<<(2 * 2 * FF * HH  / 4 + 255) / 256, 256>>>(Wp, p_wph, p_wpl, 2 * 2 * FF * HH / 4);

    for (int l = 0; l < 2; l++) {
        const __nv_bfloat16* Ah = l ? p_yh : p_xh;
        const __nv_bfloat16* Al = l ? p_yl : p_xl;
        float* OUT = l ? p_f : p_y;
        for (int dd = 0; dd < 2; dd++) {
            int w = l * 2 + dd;
            k_mma<<<dim3(GXN / 128, (TT * BB) / 128), 256, SMEM_MMA>>>(
                Ah, Al, p_wxh + (size_t)w * FF * GXN, p_wxl + (size_t)w * FF * GXN,
                bx + (size_t)w * GXN, p_gx + dd * GXSZ, GXN, FF);
            k_mma<<<dim3(HH / 128, (TT * BB) / 128), 256, SMEM_MMA>>>(
                Ah, Al, p_wph + (size_t)w * FF * HH, p_wpl + (size_t)w * FF * HH,
                bp + (size_t)w * HH, p_px + dd * PXSZ, HH, FF);
        }
        k_reset<<<256, 256>>>();
        k_rec<<<RNB, 256, REC_SMEM>>>(
            Wh + (size_t)l * 2 * HH * GXN, bh + (size_t)l * 2 * GXN,
            p_gx, p_gx + GXSZ, p_px, p_px + PXSZ, OUT);
        if (l == 0)
            k_split<<<(TT * BB * FF / 4) / 256, 256>>>(p_y, p_yh, p_yl, TT * BB * FF / 4);
    }

    k_tout<<<TT * BB, 128>>>(p_f, out);
}

// round 15
// speedup vs baseline: 1.5815x; 1.5815x over previous
#include <cuda_runtime.h>
#include <cuda_bf16.h>
#include <cstddef>
#include <cstdint>

#define TT   1024
#define BB   64
#define FF   512          // feature dim (== 2H, both layers share K=512)
#define HH   256
#define GXN  1280         // 5*H
#define NBLK 128          // recurrence blocks: 2 dirs * 64 slices

// ---------------- scratch (device globals; no runtime allocation) ------------
__device__ float g_y  [(size_t)TT*BB*FF];        // layer-0 output / layer-1 input (fp32)
__device__ float g_fin[(size_t)TT*BB*FF];        // layer-1 output
__device__ float g_gx [2][(size_t)TT*BB*GXN];    // per-dir input-gate projections
__device__ float g_px [2][(size_t)TT*BB*HH];     // per-dir highway projections
// h exchange, pre-split bf16: [parity][dir][b][k]
__device__ __nv_bfloat16 g_hh[2][2][BB*HH];
__device__ __nv_bfloat16 g_hl[2][2][BB*HH];
// per-direction barrier: 4 cells each (16 arrivals per cell per step)
__device__ __align__(16) unsigned g_bar4[2][4];

// bf16 split operands for projections
__device__ __nv_bfloat16 g_xh[(size_t)TT*BB*FF], g_xl[(size_t)TT*BB*FF];
__device__ __nv_bfloat16 g_yh[(size_t)TT*BB*FF], g_yl[(size_t)TT*BB*FF];
__device__ __nv_bfloat16 g_wxh[2*2*FF*GXN], g_wxl[2*2*FF*GXN];
__device__ __nv_bfloat16 g_wph[2*2*FF*HH],  g_wpl[2*2*FF*HH];

// ---------------- helpers ----------------------------------------------------
__device__ __forceinline__ void split1(float x, __nv_bfloat16& h, __nv_bfloat16& l) {
    h = __float2bfloat16(x);
    l = __float2bfloat16(x - __bfloat162float(h));
}

// transpose+split: features [b][t][512] fp32 -> xh/xl [t][b][512] bf16
__global__ void k_tin(const float* __restrict__ feat,
                      __nv_bfloat16* __restrict__ xh, __nv_bfloat16* __restrict__ xl) {
    int row = blockIdx.x;               // b*T + t
    int b = row >> 10, t = row & 1023;
    float4 v = ((const float4*)(feat + (size_t)row * FF))[threadIdx.x];
    size_t drow = ((size_t)t * BB + b) * FF + threadIdx.x * 4;
    __nv_bfloat16 h4[4], l4[4];
    split1(v.x, h4[0], l4[0]); split1(v.y, h4[1], l4[1]);
    split1(v.z, h4[2], l4[2]); split1(v.w, h4[3], l4[3]);
    *(uint2*)(xh + drow) = *(uint2*)h4;
    *(uint2*)(xl + drow) = *(uint2*)l4;
}

// generic fp32 -> bf16 hi/lo split (n4 = element count / 4)
__global__ void k_split(const float* __restrict__ in,
                        __nv_bfloat16* __restrict__ hi, __nv_bfloat16* __restrict__ lo, int n4) {
    int i = blockIdx.x * blockDim.x + threadIdx.x;
    if (i >= n4) return;
    float4 v = ((const float4*)in)[i];
    __nv_bfloat16 h4[4], l4[4];
    split1(v.x, h4[0], l4[0]); split1(v.y, h4[1], l4[1]);
    split1(v.z, h4[2], l4[2]); split1(v.w, h4[3], l4[3]);
    *(uint2*)(hi + (size_t)i * 4) = *(uint2*)h4;
    *(uint2*)(lo + (size_t)i * 4) = *(uint2*)l4;
}

// transpose: fin [t][b][512] -> out [b][t][512]
__global__ void k_tout(const float* __restrict__ fin, float* __restrict__ out) {
    int row = blockIdx.x;               // t*B + b
    int t = row >> 6, b = row & 63;
    const float4* s = (const float4*)(fin + (size_t)row * FF);
    float4* d = (float4*)(out + (((size_t)b << 10) + t) * FF);
    for (int i = threadIdx.x; i < FF / 4; i += blockDim.x) d[i] = s[i];
}

// ---------------- PTX wrappers -----------------------------------------------
__device__ __forceinline__ void ldsm_x4(uint32_t* r, uint32_t a) {
    asm volatile("ldmatrix.sync.aligned.m8n8.x4.shared.b16 {%0,%1,%2,%3}, [%4];"
        : "=r"(r[0]), "=r"(r[1]), "=r"(r[2]), "=r"(r[3]) : "r"(a));
}
__device__ __forceinline__ void ldsm_x4_t(uint32_t* r, uint32_t a) {
    asm volatile("ldmatrix.sync.aligned.m8n8.x4.trans.shared.b16 {%0,%1,%2,%3}, [%4];"
        : "=r"(r[0]), "=r"(r[1]), "=r"(r[2]), "=r"(r[3]) : "r"(a));
}
__device__ __forceinline__ void mma_bf16(float* c, const uint32_t* a, const uint32_t* b) {
    asm volatile("mma.sync.aligned.m16n8k16.row.col.f32.bf16.bf16.f32 "
        "{%0,%1,%2,%3},{%4,%5,%6,%7},{%8,%9},{%0,%1,%2,%3};"
        : "+f"(c[0]), "+f"(c[1]), "+f"(c[2]), "+f"(c[3])
        : "r"(a[0]), "r"(a[1]), "r"(a[2]), "r"(a[3]), "r"(b[0]), "r"(b[1]));
}
__device__ __forceinline__ void cp16(uint32_t s, const void* g) {
    asm volatile("cp.async.cg.shared.global [%0], [%1], 16;" :: "r"(s), "l"(g));
}
#define CP_COMMIT asm volatile("cp.async.commit_group;")
#define CP_WAIT1  asm volatile("cp.async.wait_group 1;")
#define CP_WAIT0  asm volatile("cp.async.wait_group 0;")

// ---------------- tensor-core split-bf16 GEMM (unchanged, proven) -------------
#define STG_A 10240               // 128 rows * 80B pitch
#define STG_B 8192                // 32 rows * 256B, XOR-swizzled
#define STG_SZ (2*STG_A + 2*STG_B)
#define SMEM_MMA (2*STG_SZ)       // double-buffered: 73728 B

__global__ __launch_bounds__(256)
void k_mma(const __nv_bfloat16* __restrict__ Ah, const __nv_bfloat16* __restrict__ Al,
           const __nv_bfloat16* __restrict__ Bh, const __nv_bfloat16* __restrict__ Bl,
           const float* __restrict__ bias, float* __restrict__ C, int N, int K) {
    extern __shared__ char smem[];
    uint32_t su = (uint32_t)__cvta_generic_to_shared(smem);
    int tid = threadIdx.x, lane = tid & 31, wid = tid >> 5;
    int mw = wid & 3, nw = wid >> 2;          // 4x2 warp grid
    int m0 = blockIdx.y * 128, n0 = blockIdx.x * 128;

    float acc[2][8][4];
#pragma unroll
    for (int mi = 0; mi < 2; mi++)
#pragma unroll
        for (int j = 0; j < 8; j++)
#pragma unroll
            for (int q = 0; q < 4; q++) acc[mi][j][q] = 0.f;

    auto load_stage = [&](int st, int k0) {
        uint32_t sa = su + st * STG_SZ;
#pragma unroll
        for (int hl = 0; hl < 2; hl++) {
            const __nv_bfloat16* Ap = hl ? Al : Ah;
            uint32_t sb = sa + hl * STG_A;
#pragma unroll
            for (int rep = 0; rep < 2; rep++) {
                int idx = tid + rep * 256;          // 0..511
                int r = idx >> 2, c = idx & 3;
                cp16(sb + r * 80 + c * 16, Ap + (size_t)(m0 + r) * K + k0 + c * 8);
            }
        }
#pragma unroll
        for (int hl = 0; hl < 2; hl++) {
            const __nv_bfloat16* Bp = hl ? Bl : Bh;
            uint32_t sb = sa + 2 * STG_A + hl * STG_B;
#pragma unroll
            for (int rep = 0; rep < 2; rep++) {
                int idx = tid + rep * 256;
                int k = idx >> 4, c = idx & 15;
                cp16(sb + k * 256 + ((c ^ (k & 7)) * 16),
                     Bp + (size_t)(k0 + k) * N + n0 + c * 8);
            }
        }
    };

    int NIT = K >> 5;                             // 16 for K=512
    load_stage(0, 0);
    CP_COMMIT;

    for (int it = 0; it < NIT; it++) {
        if (it + 1 < NIT) { load_stage((it + 1) & 1, (it + 1) * 32); CP_COMMIT; CP_WAIT1; }
        else              { CP_WAIT0; }
        __syncthreads();

        uint32_t sa = su + (it & 1) * STG_SZ;
#pragma unroll
        for (int kk = 0; kk < 2; kk++) {
            uint32_t ah[2][4], al[2][4];
            int arow_c = kk * 2 + (lane >> 4);
            int arow_r = (lane & 15);
#pragma unroll
            for (int mi = 0; mi < 2; mi++) {
                uint32_t ad = sa + (mw * 32 + mi * 16 + arow_r) * 80 + arow_c * 16;
                ldsm_x4(ah[mi], ad);
                ldsm_x4(al[mi], ad + STG_A);
            }
#pragma unroll
            for (int jp = 0; jp < 4; jp++) {
                int krow = kk * 16 + (lane & 15);
                int cch  = nw * 8 + jp * 2 + (lane >> 4);
                uint32_t bd = sa + 2 * STG_A + krow * 256 + ((cch ^ (krow & 7)) * 16);
                uint32_t bh[4], bl[4];
                ldsm_x4_t(bh, bd);
                ldsm_x4_t(bl, bd + STG_B);
#pragma unroll
                for (int jj = 0; jj < 2; jj++) {
#pragma unroll
                    for (int mi = 0; mi < 2; mi++) {
                        float* a4 = acc[mi][jp * 2 + jj];
                        mma_bf16(a4, ah[mi], &bh[jj * 2]);  // Ahi @ Bhi
                        mma_bf16(a4, ah[mi], &bl[jj * 2]);  // Ahi @ Blo
                        mma_bf16(a4, al[mi], &bh[jj * 2]);  // Alo @ Bhi
                    }
                }
            }
        }
        __syncthreads();
    }

#pragma unroll
    for (int mi = 0; mi < 2; mi++) {
#pragma unroll
        for (int j = 0; j < 8; j++) {
            int row = m0 + mw * 32 + mi * 16 + (lane >> 2);
            int col = n0 + nw * 64 + j * 8 + (lane & 3) * 2;
            float b0 = bias[col], b1 = bias[col + 1];
            float2 v0 = {acc[mi][j][0] + b0, acc[mi][j][1] + b1};
            float2 v1 = {acc[mi][j][2] + b0, acc[mi][j][3] + b1};
            *(float2*)(C + (size_t)row * N + col)       = v0;
            *(float2*)(C + (size_t)(row + 8) * N + col) = v1;
        }
    }
}

// ---------------- reset barrier + h buffers (before each recurrence) ---------
__global__ void k_reset() {
    int i = blockIdx.x * blockDim.x + threadIdx.x;
    if (i < 8) (&g_bar4[0][0])[i] = 0u;
    if (i < 2 * 2 * BB * HH / 2) {        // 32768 u32 words per array
        ((uint32_t*)g_hh)[i] = 0u;
        ((uint32_t*)g_hl)[i] = 0u;
    }
}

// ---------------- persistent tensor-core bidirectional highway-LSTM scan -----
// grid = 128 blocks: blockIdx.x = d + 2*j  (d: direction, j: 4-col slice 0..63)
// block = 256 threads = 8 warps: warp = (m-tile mt = wid&3) x (k-half k2 = wid>>2)
// Per step:
//   0. issue gx/px prefetch LDGs (independent of h), THEN wait on the
//      per-direction 4-cell barrier (poll overlaps prefetch latency)
//   1. stage pre-split h hi/lo (bf16, [b][k]) from L2 into smem (pitch 528)
//   2. mma m16n8k16 x 3 streams: z[64 b][20 n] = h @ Whslice
//   3. combine k-half partials; gate threads finish, store split h via st.cg
//   4. __syncthreads, then tid0 publishes with ONE red.release.gpu.add
//      (release orders the whole block's h stores; no per-thread threadfence)
#define R_WHI 0
#define R_WLO 20480
#define R_HHI 40960
#define R_HLO 74752
#define R_Z   108544
#define REC_SMEM (R_Z + 2*64*24*4)   // 120832

__device__ __forceinline__ float sigf(float x) { return 1.f / (1.f + expf(-x)); }

__global__ __launch_bounds__(256, 1)
void k_rec(const float* __restrict__ Wh_l,   // [2][256][1280] (this layer)
           const float* __restrict__ bh_l,   // [2][1280]
           const float* __restrict__ gx0, const float* __restrict__ gx1,
           const float* __restrict__ px0, const float* __restrict__ px1,
           float* __restrict__ outbuf) {     // [t][b][512] (fwd|bwd concat)
    extern __shared__ char smc[];
    uint32_t su = (uint32_t)__cvta_generic_to_shared(smc);
    float* zbuf = (float*)(smc + R_Z);        // [2][64][24]

    int tid = threadIdx.x, lane = tid & 31, wid = tid >> 5;
    int d  = blockIdx.x & 1;
    int j  = blockIdx.x >> 1;
    int mt = wid & 3, k2 = wid >> 2;          // warp roles
    int c  = tid & 3, b = tid >> 2;           // gate-thread element (col c, batch b)
    int col = j * 4 + c;

    const float* Wh_d = Wh_l + (size_t)d * HH * GXN;
    const float* gx = d ? gx1 : gx0;
    const float* px = d ? px1 : px0;
    unsigned* mycell = &g_bar4[d][j & 3];
    const unsigned* cells = &g_bar4[d][0];

    // fill Wh slice, split hi/lo: rows k (pitch 80B), cols n=gate*4+cc (20, pad->32 zeros)
    for (int idx = tid; idx < 256 * 32; idx += 256) {
        int k = idx >> 5, n = idx & 31;
        float v = 0.f;
        if (n < 20) v = Wh_d[(size_t)k * GXN + (n >> 2) * HH + j * 4 + (n & 3)];
        unsigned vb = __float_as_uint(v);
        unsigned short hib = (unsigned short)(vb >> 16);            // trunc split
        float lof = v - __uint_as_float(vb & 0xFFFF0000u);
        unsigned short lob;
        asm("cvt.rn.bf16.f32 %0, %1;" : "=h"(lob) : "f"(lof));
        ((unsigned short*)(smc + R_WHI + k * 80))[n] = hib;
        ((unsigned short*)(smc + R_WLO + k * 80))[n] = lob;
    }
    float bh5[5];
#pragma unroll
    for (int g = 0; g < 5; g++) bh5[g] = bh_l[(size_t)d * GXN + g * HH + col];

    float cs = 0.f;                  // cell state for (col, b)
    __syncthreads();

    for (int s = 0; s < TT; s++) {
        int t = d ? (TT - 1 - s) : s;

        // 0a. prefetch gate inputs (independent of h) BEFORE the wait
        size_t r0 = ((size_t)t * BB + b) * GXN;
        float gxa[5];
#pragma unroll
        for (int g = 0; g < 5; g++) gxa[g] = __ldg(gx + r0 + g * HH + col);
        float pxa = __ldg(px + ((size_t)t * BB + b) * HH + col);

        // 0b. wait for h(s): all 4 cells of this dir >= s*16
        if (s > 0) {
            if (tid == 0) {
                unsigned tgt = (unsigned)s * 16u;
                int spin = 0;
                while (1) {
                    unsigned v0, v1, v2, v3;
                    asm volatile("ld.volatile.global.v4.u32 {%0,%1,%2,%3}, [%4];"
                        : "=r"(v0), "=r"(v1), "=r"(v2), "=r"(v3) : "l"(cells));
                    if (v0 >= tgt && v1 >= tgt && v2 >= tgt && v3 >= tgt) break;
                    if (++spin > 4) __nanosleep(20);
                }
            }
            __syncthreads();
        }

        // 1. stage h hi/lo from L2 (chunk-rotated, conflict-free at pitch 528)
        {
            int r = tid >> 2, q = tid & 3;
            const uint4* shi = (const uint4*)&g_hh[s & 1][d][0] + r * 32 + q * 8;
            const uint4* slo = (const uint4*)&g_hl[s & 1][d][0] + r * 32 + q * 8;
            char* dhi = smc + R_HHI + r * 528 + q * 128;
            char* dlo = smc + R_HLO + r * 528 + q * 128;
#pragma unroll
            for (int i = 0; i < 8; i++) {
                int i2 = (i + q * 2) & 7;
                *(uint4*)(dhi + i2 * 16) = __ldcg(shi + i2);
                *(uint4*)(dlo + i2 * 16) = __ldcg(slo + i2);
            }
        }
        __syncthreads();

        // 2. mma: z[mt*16..+15 b][24 n] over k-half k2
        float acc[3][4];
#pragma unroll
        for (int nt = 0; nt < 3; nt++)
#pragma unroll
            for (int q = 0; q < 4; q++) acc[nt][q] = 0.f;

#pragma unroll
        for (int ks8 = 0; ks8 < 8; ks8++) {
            int ks = k2 * 8 + ks8;                // 16-k step index
            uint32_t ah[4], al[4];
            uint32_t aad = su + R_HHI + (mt * 16 + (lane & 15)) * 528
                         + ks * 32 + (lane >> 4) * 16;
            ldsm_x4(ah, aad);
            ldsm_x4(al, aad + (R_HLO - R_HHI));
            uint32_t brow = su + (ks * 16 + (lane & 15)) * 80;
            uint32_t bh0[4], bl0[4], bh1[4], bl1[4];
            ldsm_x4_t(bh0, brow + R_WHI + (0 + (lane >> 4)) * 16);
            ldsm_x4_t(bl0, brow + R_WLO + (0 + (lane >> 4)) * 16);
            ldsm_x4_t(bh1, brow + R_WHI + (2 + (lane >> 4)) * 16);
            ldsm_x4_t(bl1, brow + R_WLO + (2 + (lane >> 4)) * 16);
            mma_bf16(acc[0], ah, &bh0[0]); mma_bf16(acc[0], ah, &bl0[0]); mma_bf16(acc[0], al, &bh0[0]);
            mma_bf16(acc[1], ah, &bh0[2]); mma_bf16(acc[1], ah, &bl0[2]); mma_bf16(acc[1], al, &bh0[2]);
            mma_bf16(acc[2], ah, &bh1[0]); mma_bf16(acc[2], ah, &bl1[0]); mma_bf16(acc[2], al, &bh1[0]);
        }

        // store fragments to z[k2][batch][n]
        {
            float* zp = zbuf + k2 * (64 * 24);
            int row0 = mt * 16 + (lane >> 2);
            int col0 = (lane & 3) * 2;
#pragma unroll
            for (int nt = 0; nt < 3; nt++) {
                *(float2*)&zp[row0 * 24 + nt * 8 + col0]       = make_float2(acc[nt][0], acc[nt][1]);
                *(float2*)&zp[(row0 + 8) * 24 + nt * 8 + col0] = make_float2(acc[nt][2], acc[nt][3]);
            }
        }
        __syncthreads();

        // 3. gates for element (col, b): z split order = i, o, f, u, r
        {
            float z5[5];
#pragma unroll
            for (int g = 0; g < 5; g++) {
                int n = g * 4 + c;
                z5[g] = zbuf[b * 24 + n] + zbuf[64 * 24 + b * 24 + n];
            }
            float zi = z5[0] + gxa[0] + bh5[0];
            float zo = z5[1] + gxa[1] + bh5[1];
            float zf = z5[2] + gxa[2] + bh5[2];
            float zu = z5[3] + gxa[3] + bh5[3];
            float zr = z5[4] + gxa[4] + bh5[4];
            cs = sigf(zi) * tanhf(zu) + sigf(zf) * cs;
            float hhv = sigf(zo) * tanhf(cs);
            float rg  = sigf(zr);
            float hf  = rg * hhv + (1.f - rg) * pxa;

            // split hf -> bf16 hi (trunc) + lo (rn of residual), write via L2
            unsigned fb = __float_as_uint(hf);
            unsigned short hib = (unsigned short)(fb >> 16);
            float lof = hf - __uint_as_float(fb & 0xFFFF0000u);
            unsigned short lob;
            asm("cvt.rn.bf16.f32 %0, %1;" : "=h"(lob) : "f"(lof));
            __nv_bfloat16* dh = &g_hh[(s + 1) & 1][d][b * HH + col];
            __nv_bfloat16* dl = &g_hl[(s + 1) & 1][d][b * HH + col];
            asm volatile("st.global.cg.u16 [%0], %1;" :: "l"(dh), "h"(hib) : "memory");
            asm volatile("st.global.cg.u16 [%0], %1;" :: "l"(dl), "h"(lob) : "memory");
            outbuf[((size_t)t * BB + b) * FF + d * HH + col] = hf;
        }

        // 4. publish: syncthreads (orders block's stores), single release-atomic
        __syncthreads();
        if (tid == 0)
            asm volatile("red.release.gpu.global.add.u32 [%0], %1;"
                         :: "l"(mycell), "r"(1u) : "memory");
    }
}

// ---------------------------- host driver ------------------------------------
extern "C" void kernel_launch(void* const* d_in, const int* in_sizes, int n_in,
                              void* d_out, int out_size) {
    (void)in_sizes; (void)n_in; (void)out_size;
    const float* feat = (const float*)d_in[0];
    const float* Wx   = (const float*)d_in[1];  // [2][2][512][1280]
    const float* bx   = (const float*)d_in[2];  // [2][2][1280]
    const float* Wh   = (const float*)d_in[3];  // [2][2][256][1280]
    const float* bh   = (const float*)d_in[4];  // [2][2][1280]
    const float* Wp   = (const float*)d_in[5];  // [2][2][512][256]
    const float* bp   = (const float*)d_in[6];  // [2][2][256]
    float* out = (float*)d_out;

    float *p_y, *p_f, *p_gx, *p_px;
    __nv_bfloat16 *p_xh, *p_xl, *p_yh, *p_yl, *p_wxh, *p_wxl, *p_wph, *p_wpl;
    cudaGetSymbolAddress((void**)&p_y,   g_y);
    cudaGetSymbolAddress((void**)&p_f,   g_fin);
    cudaGetSymbolAddress((void**)&p_gx,  g_gx);
    cudaGetSymbolAddress((void**)&p_px,  g_px);
    cudaGetSymbolAddress((void**)&p_xh,  g_xh);
    cudaGetSymbolAddress((void**)&p_xl,  g_xl);
    cudaGetSymbolAddress((void**)&p_yh,  g_yh);
    cudaGetSymbolAddress((void**)&p_yl,  g_yl);
    cudaGetSymbolAddress((void**)&p_wxh, g_wxh);
    cudaGetSymbolAddress((void**)&p_wxl, g_wxl);
    cudaGetSymbolAddress((void**)&p_wph, g_wph);
    cudaGetSymbolAddress((void**)&p_wpl, g_wpl);

    cudaFuncSetAttribute(k_rec, cudaFuncAttributeMaxDynamicSharedMemorySize, REC_SMEM);
    cudaFuncSetAttribute(k_mma, cudaFuncAttributeMaxDynamicSharedMemorySize, SMEM_MMA);

    const size_t GXSZ = (size_t)TT * BB * GXN;
    const size_t PXSZ = (size_t)TT * BB * HH;

    k_tin<<<TT * BB, 128>>>(feat, p_xh, p_xl);
    k_split<<<(2 * 2 * FF * GXN / 4 + 255) / 256, 256>>>(Wx, p_wxh, p_wxl, 2 * 2 * FF * GXN / 4);
    k_split<<<(2 * 2 * FF * HH  / 4 + 255) / 256, 256>>>(Wp, p_wph, p_wpl, 2 * 2 * FF * HH / 4);

    for (int l = 0; l < 2; l++) {
        const __nv_bfloat16* Ah = l ? p_yh : p_xh;
        const __nv_bfloat16* Al = l ? p_yl : p_xl;
        float* OUT = l ? p_f : p_y;
        for (int dd = 0; dd < 2; dd++) {
            int w = l * 2 + dd;
            k_mma<<<dim3(GXN / 128, (TT * BB) / 128), 256, SMEM_MMA>>>(
                Ah, Al, p_wxh + (size_t)w * FF * GXN, p_wxl + (size_t)w * FF * GXN,
                bx + (size_t)w * GXN, p_gx + dd * GXSZ, GXN, FF);
            k_mma<<<dim3(HH / 128, (TT * BB) / 128), 256, SMEM_MMA>>>(
                Ah, Al, p_wph + (size_t)w * FF * HH, p_wpl + (size_t)w * FF * HH,
                bp + (size_t)w * HH, p_px + dd * PXSZ, HH, FF);
        }
        k_reset<<<256, 256>>>();
        k_rec<<<NBLK, 256, REC_SMEM>>>(
            Wh + (size_t)l * 2 * HH * GXN, bh + (size_t)l * 2 * GXN,
            p_gx, p_gx + GXSZ, p_px, p_px + PXSZ, OUT);
        if (l == 0)
            k_split<<<(TT * BB * FF / 4) / 256, 256>>>(p_y, p_yh, p_yl, TT * BB * FF / 4);
    }

    k_tout<<<TT * BB, 128>>>(p_f, out);
}

// round 16
// speedup vs baseline: 1.7041x; 1.0776x over previous
#include <cuda_runtime.h>
#include <cuda_bf16.h>
#include <cstddef>
#include <cstdint>

#define TT   1024
#define BB   64
#define FF   512          // feature dim (== 2H, both layers share K=512)
#define HH   256
#define GXN  1280         // 5*H
#define NBLK 128          // recurrence blocks: 2 dirs * 64 slices

// ---------------- scratch (device globals; no runtime allocation) ------------
__device__ float g_y  [(size_t)TT*BB*FF];        // layer-0 output / layer-1 input (fp32)
__device__ float g_fin[(size_t)TT*BB*FF];        // layer-1 output
__device__ float g_gx [2][(size_t)TT*BB*GXN];    // per-dir input-gate projections
__device__ float g_px [2][(size_t)TT*BB*HH];     // per-dir highway projections
// h exchange, pre-split bf16: [parity][dir][b][k]
__device__ __align__(16) __nv_bfloat16 g_hh[2][2][BB*HH];
__device__ __align__(16) __nv_bfloat16 g_hl[2][2][BB*HH];
// per-direction barrier: 4 cells each (16 arrivals per cell per step)
__device__ __align__(16) unsigned g_bar4[2][4];

// bf16 split operands for projections
__device__ __nv_bfloat16 g_xh[(size_t)TT*BB*FF], g_xl[(size_t)TT*BB*FF];
__device__ __nv_bfloat16 g_yh[(size_t)TT*BB*FF], g_yl[(size_t)TT*BB*FF];
__device__ __nv_bfloat16 g_wxh[2*2*FF*GXN], g_wxl[2*2*FF*GXN];
__device__ __nv_bfloat16 g_wph[2*2*FF*HH],  g_wpl[2*2*FF*HH];

// ---------------- helpers ----------------------------------------------------
__device__ __forceinline__ void split1(float x, __nv_bfloat16& h, __nv_bfloat16& l) {
    h = __float2bfloat16(x);
    l = __float2bfloat16(x - __bfloat162float(h));
}

// transpose+split: features [b][t][512] fp32 -> xh/xl [t][b][512] bf16
__global__ void k_tin(const float* __restrict__ feat,
                      __nv_bfloat16* __restrict__ xh, __nv_bfloat16* __restrict__ xl) {
    int row = blockIdx.x;               // b*T + t
    int b = row >> 10, t = row & 1023;
    float4 v = ((const float4*)(feat + (size_t)row * FF))[threadIdx.x];
    size_t drow = ((size_t)t * BB + b) * FF + threadIdx.x * 4;
    __nv_bfloat16 h4[4], l4[4];
    split1(v.x, h4[0], l4[0]); split1(v.y, h4[1], l4[1]);
    split1(v.z, h4[2], l4[2]); split1(v.w, h4[3], l4[3]);
    *(uint2*)(xh + drow) = *(uint2*)h4;
    *(uint2*)(xl + drow) = *(uint2*)l4;
}

// generic fp32 -> bf16 hi/lo split (n4 = element count / 4)
__global__ void k_split(const float* __restrict__ in,
                        __nv_bfloat16* __restrict__ hi, __nv_bfloat16* __restrict__ lo, int n4) {
    int i = blockIdx.x * blockDim.x + threadIdx.x;
    if (i >= n4) return;
    float4 v = ((const float4*)in)[i];
    __nv_bfloat16 h4[4], l4[4];
    split1(v.x, h4[0], l4[0]); split1(v.y, h4[1], l4[1]);
    split1(v.z, h4[2], l4[2]); split1(v.w, h4[3], l4[3]);
    *(uint2*)(hi + (size_t)i * 4) = *(uint2*)h4;
    *(uint2*)(lo + (size_t)i * 4) = *(uint2*)l4;
}

// transpose: fin [t][b][512] -> out [b][t][512]
__global__ void k_tout(const float* __restrict__ fin, float* __restrict__ out) {
    int row = blockIdx.x;               // t*B + b
    int t = row >> 6, b = row & 63;
    const float4* s = (const float4*)(fin + (size_t)row * FF);
    float4* d = (float4*)(out + (((size_t)b << 10) + t) * FF);
    for (int i = threadIdx.x; i < FF / 4; i += blockDim.x) d[i] = s[i];
}

// ---------------- PTX wrappers -----------------------------------------------
__device__ __forceinline__ void ldsm_x4(uint32_t* r, uint32_t a) {
    asm volatile("ldmatrix.sync.aligned.m8n8.x4.shared.b16 {%0,%1,%2,%3}, [%4];"
        : "=r"(r[0]), "=r"(r[1]), "=r"(r[2]), "=r"(r[3]) : "r"(a));
}
__device__ __forceinline__ void ldsm_x4_t(uint32_t* r, uint32_t a) {
    asm volatile("ldmatrix.sync.aligned.m8n8.x4.trans.shared.b16 {%0,%1,%2,%3}, [%4];"
        : "=r"(r[0]), "=r"(r[1]), "=r"(r[2]), "=r"(r[3]) : "r"(a));
}
__device__ __forceinline__ void ldsm_x2_t(uint32_t* r, uint32_t a) {
    asm volatile("ldmatrix.sync.aligned.m8n8.x2.trans.shared.b16 {%0,%1}, [%2];"
        : "=r"(r[0]), "=r"(r[1]) : "r"(a));
}
__device__ __forceinline__ void mma_bf16(float* c, const uint32_t* a, const uint32_t* b) {
    asm volatile("mma.sync.aligned.m16n8k16.row.col.f32.bf16.bf16.f32 "
        "{%0,%1,%2,%3},{%4,%5,%6,%7},{%8,%9},{%0,%1,%2,%3};"
        : "+f"(c[0]), "+f"(c[1]), "+f"(c[2]), "+f"(c[3])
        : "r"(a[0]), "r"(a[1]), "r"(a[2]), "r"(a[3]), "r"(b[0]), "r"(b[1]));
}
__device__ __forceinline__ void cp16(uint32_t s, const void* g) {
    asm volatile("cp.async.cg.shared.global [%0], [%1], 16;" :: "r"(s), "l"(g));
}
#define CP_COMMIT asm volatile("cp.async.commit_group;")
#define CP_WAIT1  asm volatile("cp.async.wait_group 1;")
#define CP_WAIT0  asm volatile("cp.async.wait_group 0;")

// ---------------- tensor-core split-bf16 GEMM (unchanged, proven) -------------
#define STG_A 10240               // 128 rows * 80B pitch
#define STG_B 8192                // 32 rows * 256B, XOR-swizzled
#define STG_SZ (2*STG_A + 2*STG_B)
#define SMEM_MMA (2*STG_SZ)       // double-buffered: 73728 B

__global__ __launch_bounds__(256)
void k_mma(const __nv_bfloat16* __restrict__ Ah, const __nv_bfloat16* __restrict__ Al,
           const __nv_bfloat16* __restrict__ Bh, const __nv_bfloat16* __restrict__ Bl,
           const float* __restrict__ bias, float* __restrict__ C, int N, int K) {
    extern __shared__ char smem[];
    uint32_t su = (uint32_t)__cvta_generic_to_shared(smem);
    int tid = threadIdx.x, lane = tid & 31, wid = tid >> 5;
    int mw = wid & 3, nw = wid >> 2;          // 4x2 warp grid
    int m0 = blockIdx.y * 128, n0 = blockIdx.x * 128;

    float acc[2][8][4];
#pragma unroll
    for (int mi = 0; mi < 2; mi++)
#pragma unroll
        for (int j = 0; j < 8; j++)
#pragma unroll
            for (int q = 0; q < 4; q++) acc[mi][j][q] = 0.f;

    auto load_stage = [&](int st, int k0) {
        uint32_t sa = su + st * STG_SZ;
#pragma unroll
        for (int hl = 0; hl < 2; hl++) {
            const __nv_bfloat16* Ap = hl ? Al : Ah;
            uint32_t sb = sa + hl * STG_A;
#pragma unroll
            for (int rep = 0; rep < 2; rep++) {
                int idx = tid + rep * 256;          // 0..511
                int r = idx >> 2, c = idx & 3;
                cp16(sb + r * 80 + c * 16, Ap + (size_t)(m0 + r) * K + k0 + c * 8);
            }
        }
#pragma unroll
        for (int hl = 0; hl < 2; hl++) {
            const __nv_bfloat16* Bp = hl ? Bl : Bh;
            uint32_t sb = sa + 2 * STG_A + hl * STG_B;
#pragma unroll
            for (int rep = 0; rep < 2; rep++) {
                int idx = tid + rep * 256;
                int k = idx >> 4, c = idx & 15;
                cp16(sb + k * 256 + ((c ^ (k & 7)) * 16),
                     Bp + (size_t)(k0 + k) * N + n0 + c * 8);
            }
        }
    };

    int NIT = K >> 5;                             // 16 for K=512
    load_stage(0, 0);
    CP_COMMIT;

    for (int it = 0; it < NIT; it++) {
        if (it + 1 < NIT) { load_stage((it + 1) & 1, (it + 1) * 32); CP_COMMIT; CP_WAIT1; }
        else              { CP_WAIT0; }
        __syncthreads();

        uint32_t sa = su + (it & 1) * STG_SZ;
#pragma unroll
        for (int kk = 0; kk < 2; kk++) {
            uint32_t ah[2][4], al[2][4];
            int arow_c = kk * 2 + (lane >> 4);
            int arow_r = (lane & 15);
#pragma unroll
            for (int mi = 0; mi < 2; mi++) {
                uint32_t ad = sa + (mw * 32 + mi * 16 + arow_r) * 80 + arow_c * 16;
                ldsm_x4(ah[mi], ad);
                ldsm_x4(al[mi], ad + STG_A);
            }
#pragma unroll
            for (int jp = 0; jp < 4; jp++) {
                int krow = kk * 16 + (lane & 15);
                int cch  = nw * 8 + jp * 2 + (lane >> 4);
                uint32_t bd = sa + 2 * STG_A + krow * 256 + ((cch ^ (krow & 7)) * 16);
                uint32_t bh[4], bl[4];
                ldsm_x4_t(bh, bd);
                ldsm_x4_t(bl, bd + STG_B);
#pragma unroll
                for (int jj = 0; jj < 2; jj++) {
#pragma unroll
                    for (int mi = 0; mi < 2; mi++) {
                        float* a4 = acc[mi][jp * 2 + jj];
                        mma_bf16(a4, ah[mi], &bh[jj * 2]);  // Ahi @ Bhi
                        mma_bf16(a4, ah[mi], &bl[jj * 2]);  // Ahi @ Blo
                        mma_bf16(a4, al[mi], &bh[jj * 2]);  // Alo @ Bhi
                    }
                }
            }
        }
        __syncthreads();
    }

#pragma unroll
    for (int mi = 0; mi < 2; mi++) {
#pragma unroll
        for (int j = 0; j < 8; j++) {
            int row = m0 + mw * 32 + mi * 16 + (lane >> 2);
            int col = n0 + nw * 64 + j * 8 + (lane & 3) * 2;
            float b0 = bias[col], b1 = bias[col + 1];
            float2 v0 = {acc[mi][j][0] + b0, acc[mi][j][1] + b1};
            float2 v1 = {acc[mi][j][2] + b0, acc[mi][j][3] + b1};
            *(float2*)(C + (size_t)row * N + col)       = v0;
            *(float2*)(C + (size_t)(row + 8) * N + col) = v1;
        }
    }
}

// ---------------- reset barrier + h buffers (before each recurrence) ---------
__global__ void k_reset() {
    int i = blockIdx.x * blockDim.x + threadIdx.x;
    if (i < 8) (&g_bar4[0][0])[i] = 0u;
    if (i < 2 * 2 * BB * HH / 2) {        // 32768 u32 words per array
        ((uint32_t*)g_hh)[i] = 0u;
        ((uint32_t*)g_hl)[i] = 0u;
    }
}

// ---------------- persistent tensor-core bidirectional highway-LSTM scan -----
// grid = 128 blocks: blockIdx.x = d + 2*j  (d: direction, j: 4-col slice 0..63)
// block = 256 threads = 8 warps: warp = (m-tile mt = wid&3) x (k-half k2 = wid>>2)
// W (Wh slice) fragments are hoisted into REGISTERS once (96 regs/thread);
// the step loop does: gx prefetch -> barrier wait -> cp.async h staging ->
// 16 A-ldsm + 72 mma -> z combine -> fast gates -> h store -> publish -> outbuf.
// smem: zbuf overlays the W staging planes (free after the register preload).
#define R_WHI 0
#define R_WLO 20480
#define R_HHI 40960
#define R_HLO 74752
#define REC_SMEM (R_HLO + 33792)   // 108544
#define R_Z   0                    // zbuf overlays W planes after preload

__device__ __forceinline__ float fsig(float x) {
    return __fdividef(1.f, 1.f + __expf(-x));
}
__device__ __forceinline__ float ftanhf(float x) {
    return __fdividef(2.f, 1.f + __expf(-2.f * x)) - 1.f;
}

__global__ __launch_bounds__(256, 1)
void k_rec(const float* __restrict__ Wh_l,   // [2][256][1280] (this layer)
           const float* __restrict__ bh_l,   // [2][1280]
           const float* __restrict__ gx0, const float* __restrict__ gx1,
           const float* __restrict__ px0, const float* __restrict__ px1,
           float* __restrict__ outbuf) {     // [t][b][512] (fwd|bwd concat)
    extern __shared__ char smc[];
    uint32_t su = (uint32_t)__cvta_generic_to_shared(smc);
    float* zbuf = (float*)(smc + R_Z);        // [2][64][24] (overlays W planes)

    int tid = threadIdx.x, lane = tid & 31, wid = tid >> 5;
    int d  = blockIdx.x & 1;
    int j  = blockIdx.x >> 1;
    int mt = wid & 3, k2 = wid >> 2;          // warp roles
    int c  = tid & 3, b = tid >> 2;           // gate-thread element (col c, batch b)
    int col = j * 4 + c;

    const float* Wh_d = Wh_l + (size_t)d * HH * GXN;
    const float* gx = d ? gx1 : gx0;
    const float* px = d ? px1 : px0;
    unsigned* mycell = &g_bar4[d][j & 3];
    const unsigned* cells = &g_bar4[d][0];

    // fill Wh slice into smem, split hi/lo (pitch 80B, n padded to 32 w/ zeros)
    for (int idx = tid; idx < 256 * 32; idx += 256) {
        int k = idx >> 5, n = idx & 31;
        float v = 0.f;
        if (n < 20) v = Wh_d[(size_t)k * GXN + (n >> 2) * HH + j * 4 + (n & 3)];
        unsigned vb = __float_as_uint(v);
        unsigned short hib = (unsigned short)(vb >> 16);            // trunc split
        float lof = v - __uint_as_float(vb & 0xFFFF0000u);
        unsigned short lob;
        asm("cvt.rn.bf16.f32 %0, %1;" : "=h"(lob) : "f"(lof));
        ((unsigned short*)(smc + R_WHI + k * 80))[n] = hib;
        ((unsigned short*)(smc + R_WLO + k * 80))[n] = lob;
    }
    float bh5[5];
#pragma unroll
    for (int g = 0; g < 5; g++) bh5[g] = bh_l[(size_t)d * GXN + g * HH + col];
    __syncthreads();

    // hoist W fragments into registers (time-invariant across all 1024 steps)
    uint32_t wh0[8][4], wl0[8][4], wh1[8][2], wl1[8][2];
#pragma unroll
    for (int ks8 = 0; ks8 < 8; ks8++) {
        int ks = k2 * 8 + ks8;
        uint32_t brow = su + (ks * 16 + (lane & 15)) * 80;
        ldsm_x4_t(wh0[ks8], brow + R_WHI + (lane >> 4) * 16);
        ldsm_x4_t(wl0[ks8], brow + R_WLO + (lane >> 4) * 16);
        ldsm_x2_t(wh1[ks8], brow + R_WHI + 32);
        ldsm_x2_t(wl1[ks8], brow + R_WLO + 32);
    }
    __syncthreads();   // W planes now free -> zbuf may overlay them

    float cs = 0.f;                  // cell state for (col, b)

    for (int s = 0; s < TT; s++) {
        int t = d ? (TT - 1 - s) : s;

        // 0a. prefetch gate inputs (independent of h) BEFORE the wait
        size_t r0 = ((size_t)t * BB + b) * GXN;
        float gxa[5];
#pragma unroll
        for (int g = 0; g < 5; g++) gxa[g] = __ldg(gx + r0 + g * HH + col);
        float pxa = __ldg(px + ((size_t)t * BB + b) * HH + col);

        // 0b. wait for h(s): all 4 cells of this dir >= s*16
        if (s > 0) {
            if (tid == 0) {
                unsigned tgt = (unsigned)s * 16u;
                int spin = 0;
                while (1) {
                    unsigned v0, v1, v2, v3;
                    asm volatile("ld.volatile.global.v4.u32 {%0,%1,%2,%3}, [%4];"
                        : "=r"(v0), "=r"(v1), "=r"(v2), "=r"(v3) : "l"(cells));
                    if (v0 >= tgt && v1 >= tgt && v2 >= tgt && v3 >= tgt) break;
                    if (++spin > 16) __nanosleep(20);
                }
            }
            __syncthreads();
        }

        // 1. stage h hi/lo via cp.async (chunk-rotated, conflict-free @528)
        {
            int r = tid >> 2, q = tid & 3;
            const uint4* shi = (const uint4*)&g_hh[s & 1][d][0] + r * 32 + q * 8;
            const uint4* slo = (const uint4*)&g_hl[s & 1][d][0] + r * 32 + q * 8;
            uint32_t dhi = su + R_HHI + r * 528 + q * 128;
            uint32_t dlo = su + R_HLO + r * 528 + q * 128;
#pragma unroll
            for (int i = 0; i < 8; i++) {
                int i2 = (i + q * 2) & 7;
                cp16(dhi + i2 * 16, shi + i2);
                cp16(dlo + i2 * 16, slo + i2);
            }
        }
        CP_COMMIT;
        CP_WAIT0;
        __syncthreads();

        // 2. mma: z[mt*16..+15 b][24 n] over k-half k2 (W frags in registers)
        float acc[3][4];
#pragma unroll
        for (int nt = 0; nt < 3; nt++)
#pragma unroll
            for (int q = 0; q < 4; q++) acc[nt][q] = 0.f;

#pragma unroll
        for (int ks8 = 0; ks8 < 8; ks8++) {
            int ks = k2 * 8 + ks8;                // 16-k step index
            uint32_t ah[4], al[4];
            uint32_t aad = su + R_HHI + (mt * 16 + (lane & 15)) * 528
                         + ks * 32 + (lane >> 4) * 16;
            ldsm_x4(ah, aad);
            ldsm_x4(al, aad + (R_HLO - R_HHI));
            mma_bf16(acc[0], ah, &wh0[ks8][0]); mma_bf16(acc[0], ah, &wl0[ks8][0]); mma_bf16(acc[0], al, &wh0[ks8][0]);
            mma_bf16(acc[1], ah, &wh0[ks8][2]); mma_bf16(acc[1], ah, &wl0[ks8][2]); mma_bf16(acc[1], al, &wh0[ks8][2]);
            mma_bf16(acc[2], ah, &wh1[ks8][0]); mma_bf16(acc[2], ah, &wl1[ks8][0]); mma_bf16(acc[2], al, &wh1[ks8][0]);
        }

        // store fragments to z[k2][batch][n]
        {
            float* zp = zbuf + k2 * (64 * 24);
            int row0 = mt * 16 + (lane >> 2);
            int col0 = (lane & 3) * 2;
#pragma unroll
            for (int nt = 0; nt < 3; nt++) {
                *(float2*)&zp[row0 * 24 + nt * 8 + col0]       = make_float2(acc[nt][0], acc[nt][1]);
                *(float2*)&zp[(row0 + 8) * 24 + nt * 8 + col0] = make_float2(acc[nt][2], acc[nt][3]);
            }
        }
        __syncthreads();

        // 3. gates for element (col, b): z split order = i, o, f, u, r
        float hf;
        {
            float z5[5];
#pragma unroll
            for (int g = 0; g < 5; g++) {
                int n = g * 4 + c;
                z5[g] = zbuf[b * 24 + n] + zbuf[64 * 24 + b * 24 + n];
            }
            float zi = z5[0] + gxa[0] + bh5[0];
            float zo = z5[1] + gxa[1] + bh5[1];
            float zf = z5[2] + gxa[2] + bh5[2];
            float zu = z5[3] + gxa[3] + bh5[3];
            float zr = z5[4] + gxa[4] + bh5[4];
            cs = fsig(zi) * ftanhf(zu) + fsig(zf) * cs;
            float hhv = fsig(zo) * ftanhf(cs);
            float rg  = fsig(zr);
            hf = rg * hhv + (1.f - rg) * pxa;

            // split hf -> bf16 hi (trunc) + lo (rn of residual), write via L2
            unsigned fb = __float_as_uint(hf);
            unsigned short hib = (unsigned short)(fb >> 16);
            float lof = hf - __uint_as_float(fb & 0xFFFF0000u);
            unsigned short lob;
            asm("cvt.rn.bf16.f32 %0, %1;" : "=h"(lob) : "f"(lof));
            __nv_bfloat16* dh = &g_hh[(s + 1) & 1][d][b * HH + col];
            __nv_bfloat16* dl = &g_hl[(s + 1) & 1][d][b * HH + col];
            asm volatile("st.global.cg.u16 [%0], %1;" :: "l"(dh), "h"(hib) : "memory");
            asm volatile("st.global.cg.u16 [%0], %1;" :: "l"(dl), "h"(lob) : "memory");
        }

        // 4. publish ASAP: syncthreads (orders h stores), single release-atomic
        __syncthreads();
        if (tid == 0)
            asm volatile("red.release.gpu.global.add.u32 [%0], %1;"
                         :: "l"(mycell), "r"(1u) : "memory");

        // 5. outbuf store AFTER publish (off the inter-block critical path)
        outbuf[((size_t)t * BB + b) * FF + d * HH + col] = hf;
    }
}

// ---------------------------- host driver ------------------------------------
extern "C" void kernel_launch(void* const* d_in, const int* in_sizes, int n_in,
                              void* d_out, int out_size) {
    (void)in_sizes; (void)n_in; (void)out_size;
    const float* feat = (const float*)d_in[0];
    const float* Wx   = (const float*)d_in[1];  // [2][2][512][1280]
    const float* bx   = (const float*)d_in[2];  // [2][2][1280]
    const float* Wh   = (const float*)d_in[3];  // [2][2][256][1280]
    const float* bh   = (const float*)d_in[4];  // [2][2][1280]
    const float* Wp   = (const float*)d_in[5];  // [2][2][512][256]
    const float* bp   = (const float*)d_in[6];  // [2][2][256]
    float* out = (float*)d_out;

    float *p_y, *p_f, *p_gx, *p_px;
    __nv_bfloat16 *p_xh, *p_xl, *p_yh, *p_yl, *p_wxh, *p_wxl, *p_wph, *p_wpl;
    cudaGetSymbolAddress((void**)&p_y,   g_y);
    cudaGetSymbolAddress((void**)&p_f,   g_fin);
    cudaGetSymbolAddress((void**)&p_gx,  g_gx);
    cudaGetSymbolAddress((void**)&p_px,  g_px);
    cudaGetSymbolAddress((void**)&p_xh,  g_xh);
    cudaGetSymbolAddress((void**)&p_xl,  g_xl);
    cudaGetSymbolAddress((void**)&p_yh,  g_yh);
    cudaGetSymbolAddress((void**)&p_yl,  g_yl);
    cudaGetSymbolAddress((void**)&p_wxh, g_wxh);
    cudaGetSymbolAddress((void**)&p_wxl, g_wxl);
    cudaGetSymbolAddress((void**)&p_wph, g_wph);
    cudaGetSymbolAddress((void**)&p_wpl, g_wpl);

    cudaFuncSetAttribute(k_rec, cudaFuncAttributeMaxDynamicSharedMemorySize, REC_SMEM);
    cudaFuncSetAttribute(k_mma, cudaFuncAttributeMaxDynamicSharedMemorySize, SMEM_MMA);

    const size_t GXSZ = (size_t)TT * BB * GXN;
    const size_t PXSZ = (size_t)TT * BB * HH;

    k_tin<<<TT * BB, 128>>>(feat, p_xh, p_xl);
    k_split<<<(2 * 2 * FF * GXN / 4 + 255) / 256, 256>>>(Wx, p_wxh, p_wxl, 2 * 2 * FF * GXN / 4);
    k_split<<<(2 * 2 * FF * HH  / 4 + 255) / 256, 256>>>(Wp, p_wph, p_wpl, 2 * 2 * FF * HH / 4);

    for (int l = 0; l < 2; l++) {
        const __nv_bfloat16* Ah = l ? p_yh : p_xh;
        const __nv_bfloat16* Al = l ? p_yl : p_xl;
        float* OUT = l ? p_f : p_y;
        for (int dd = 0; dd < 2; dd++) {
            int w = l * 2 + dd;
            k_mma<<<dim3(GXN / 128, (TT * BB) / 128), 256, SMEM_MMA>>>(
                Ah, Al, p_wxh + (size_t)w * FF * GXN, p_wxl + (size_t)w * FF * GXN,
                bx + (size_t)w * GXN, p_gx + dd * GXSZ, GXN, FF);
            k_mma<<<dim3(HH / 128, (TT * BB) / 128), 256, SMEM_MMA>>>(
                Ah, Al, p_wph + (size_t)w * FF * HH, p_wpl + (size_t)w * FF * HH,
                bp + (size_t)w * HH, p_px + dd * PXSZ, HH, FF);
        }
        k_reset<<<256, 256>>>();
        k_rec<<<NBLK, 256, REC_SMEM>>>(
            Wh + (size_t)l * 2 * HH * GXN, bh + (size_t)l * 2 * GXN,
            p_gx, p_gx + GXSZ, p_px, p_px + PXSZ, OUT);
        if (l == 0)
            k_split<<<(TT * BB * FF / 4) / 256, 256>>>(p_y, p_yh, p_yl, TT * BB * FF / 4);
    }

    k_tout<<<TT * BB, 128>>>(p_f, out);
}